// round 13
// baseline (speedup 1.0000x reference)
#include <cuda_runtime.h>
#include <cuda_bf16.h>
#include <cuda_fp16.h>
#include <cstdint>

#define BB 4
#define SS 2048
#define DD 1024
#define HH 16
#define HDIM 64
#define MROWS (BB*SS)   // 8192
#define QSCALE 0.1803368801111204f   // log2(e)/8
#define NSM_CTAS 296    // 148 SMs * 2 CTAs

// ---------------------------------------------------------------------------
// Scratch (device globals; allocation-free)
// ---------------------------------------------------------------------------
__device__ __align__(128) float g_T[MROWS*DD];
__device__ __align__(128) float g_H[MROWS*DD];

__device__ __align__(128) __half g_xf[MROWS*DD];
__device__ __align__(128) __half g_Qf[MROWS*DD];   // head-major, pre-scaled
__device__ __align__(128) __half g_Kf[MROWS*DD];   // head-major
__device__ __align__(128) __half g_Vf[MROWS*DD];   // head-major
__device__ __align__(128) __half g_AVf[MROWS*DD];
__device__ __align__(128) __half g_Hf[MROWS*DD];
__device__ __align__(128) __half g_Ff[MROWS*DD];

__device__ __align__(128) __half g_Wq[DD*DD];
__device__ __align__(128) __half g_Wk[DD*DD];
__device__ __align__(128) __half g_Wv[DD*DD];
__device__ __align__(128) __half g_Wo[DD*DD];
__device__ __align__(128) __half g_W1[DD*DD];
__device__ __align__(128) __half g_W2[DD*DD];

// ---------------------------------------------------------------------------
// Helpers
// ---------------------------------------------------------------------------
__device__ __forceinline__ uint32_t smem_u32(const void* p) {
    uint32_t a;
    asm("{ .reg .u64 t; cvta.to.shared.u64 t, %1; cvt.u32.u64 %0, t; }"
        : "=r"(a) : "l"(p));
    return a;
}
__device__ __forceinline__ void cpa16(uint32_t saddr, const void* g) {
    asm volatile("cp.async.cg.shared.global [%0], [%1], 16;"
                 :: "r"(saddr), "l"(g) : "memory");
}
#define CP_COMMIT() asm volatile("cp.async.commit_group;" ::: "memory")
#define CP_WAIT(n)  asm volatile("cp.async.wait_group %0;" :: "n"(n) : "memory")

__device__ __forceinline__ void ldsm4(uint32_t* r, uint32_t a) {
    asm volatile("ldmatrix.sync.aligned.m8n8.x4.shared.b16 {%0,%1,%2,%3}, [%4];"
        : "=r"(r[0]), "=r"(r[1]), "=r"(r[2]), "=r"(r[3]) : "r"(a));
}
__device__ __forceinline__ void ldsm4t(uint32_t* r, uint32_t a) {
    asm volatile("ldmatrix.sync.aligned.m8n8.x4.trans.shared.b16 {%0,%1,%2,%3}, [%4];"
        : "=r"(r[0]), "=r"(r[1]), "=r"(r[2]), "=r"(r[3]) : "r"(a));
}
__device__ __forceinline__ void mma_f16(float* c, const uint32_t* a,
                                        uint32_t b0, uint32_t b1) {
    asm volatile("mma.sync.aligned.m16n8k16.row.col.f32.f16.f16.f32 "
        "{%0,%1,%2,%3}, {%4,%5,%6,%7}, {%8,%9}, {%0,%1,%2,%3};"
        : "+f"(c[0]), "+f"(c[1]), "+f"(c[2]), "+f"(c[3])
        : "r"(a[0]), "r"(a[1]), "r"(a[2]), "r"(a[3]), "r"(b0), "r"(b1));
}
// d = a*b + 0
__device__ __forceinline__ void mma_f16_z(float* d, const uint32_t* a,
                                          uint32_t b0, uint32_t b1) {
    asm volatile("mma.sync.aligned.m16n8k16.row.col.f32.f16.f16.f32 "
        "{%0,%1,%2,%3}, {%4,%5,%6,%7}, {%8,%9}, {%10,%10,%10,%10};"
        : "=f"(d[0]), "=f"(d[1]), "=f"(d[2]), "=f"(d[3])
        : "r"(a[0]), "r"(a[1]), "r"(a[2]), "r"(a[3]), "r"(b0), "r"(b1),
          "f"(0.f));
}
// 128B-row XOR swizzle (64 f16 per row, 8 chunks of 16B)
__device__ __forceinline__ uint32_t swoff(int row, int chunk) {
    return (uint32_t)(row * 128 + ((chunk ^ (row & 7)) << 4));
}
__device__ __forceinline__ uint32_t frag_addr(uint32_t base, int r0, int kstep) {
    int lane = threadIdx.x & 31;
    int row = r0 + (lane & 15);
    int chunk = kstep * 2 + (lane >> 4);
    return base + swoff(row, chunk);
}
__device__ __forceinline__ uint32_t fragV_addr(uint32_t base, int kb, int dpair) {
    int lane = threadIdx.x & 31;
    int row = kb + (lane & 7) + ((lane & 16) >> 1);
    int chunk = dpair * 2 + ((lane >> 3) & 1);
    return base + swoff(row, chunk);
}
__device__ __forceinline__ uint32_t packh2(float a, float b) {
    __half2 t = __floats2half2_rn(a, b);
    return *reinterpret_cast<uint32_t*>(&t);
}
__device__ __forceinline__ uint32_t ex2_pack(float a, float b) {
    __half2 hx = __floats2half2_rn(a, b);
    uint32_t u = *reinterpret_cast<uint32_t*>(&hx);
    asm("ex2.approx.f16x2 %0, %0;" : "+r"(u));
    return u;
}

// ---------------------------------------------------------------------------
// Batched weight prep: 6 weights [K,N] fp32 -> [N,K] f16, one launch
// ---------------------------------------------------------------------------
__global__ __launch_bounds__(256)
void wsplit_all(const float* __restrict__ W0, const float* __restrict__ W1,
                const float* __restrict__ W2, const float* __restrict__ W3,
                const float* __restrict__ W4, const float* __restrict__ W5,
                __half* __restrict__ T0, __half* __restrict__ T1,
                __half* __restrict__ T2, __half* __restrict__ T3,
                __half* __restrict__ T4, __half* __restrict__ T5)
{
    const float* W; __half* T;
    switch (blockIdx.z) {
        case 0: W = W0; T = T0; break;
        case 1: W = W1; T = T1; break;
        case 2: W = W2; T = T2; break;
        case 3: W = W3; T = T3; break;
        case 4: W = W4; T = T4; break;
        default: W = W5; T = T5; break;
    }
    __shared__ float tile[32][33];
    const int bn = blockIdx.x * 32;
    const int bk = blockIdx.y * 32;
    const int tx = threadIdx.x & 31, ty = threadIdx.x >> 5;
#pragma unroll
    for (int i = ty; i < 32; i += 8)
        tile[i][tx] = W[(size_t)(bk + i) * DD + bn + tx];
    __syncthreads();
#pragma unroll
    for (int i = ty; i < 32; i += 8)
        T[(size_t)(bn + i) * DD + bk + tx] = __float2half_rn(tile[tx][i]);
}

// fp32 -> f16 convert (layout-preserving)
__global__ __launch_bounds__(256)
void xcvt_kernel(const float* __restrict__ X, __half* __restrict__ Xf)
{
    size_t i = ((size_t)blockIdx.x * 256 + threadIdx.x) * 4;
    float4 v = *(const float4*)(X + i);
    *(uint2*)(Xf + i) = make_uint2(packh2(v.x, v.y), packh2(v.z, v.w));
}

// ---------------------------------------------------------------------------
// Dense GEMM core: 128 threads = 4 warps (2m x 2n), warp tile 64x64,
// CTA 128x128, k-chunk 64, 3-stage cp.async (32KB/stage, cyclic ptrs).
// ---------------------------------------------------------------------------
#define G_STAGE 32768
#define G_SMEM  (3 * G_STAGE)   // 98304
#define G_TILES 512             // 64 m-tiles * 8 n-tiles

__device__ __forceinline__ void g_issue(uint32_t st,
    const __half* A, const __half* B, int m0, int n0, int kc0, int tid)
{
#pragma unroll
    for (int it = 0; it < 8; it++) {
        int f = it * 128 + tid;
        int row = f >> 3, c = f & 7;
        uint32_t off = swoff(row, c);
        cpa16(st + off,         A + (size_t)(m0 + row) * DD + kc0 + c * 8);
        cpa16(st + 16384 + off, B + (size_t)(n0 + row) * DD + kc0 + c * 8);
    }
}
__device__ __forceinline__ void g_mma64(uint32_t base, int wm, int wn,
                                        float acc[4][8][4])
{
#pragma unroll
    for (int j = 0; j < 4; j++) {
        uint32_t a[4][4], b[4][4];
#pragma unroll
        for (int i = 0; i < 4; i++)
            ldsm4(a[i], frag_addr(base, wm * 64 + i * 16, j));
#pragma unroll
        for (int i = 0; i < 4; i++)
            ldsm4(b[i], frag_addr(base + 16384, wn * 64 + i * 16, j));
#pragma unroll
        for (int mf = 0; mf < 4; mf++)
#pragma unroll
            for (int nf = 0; nf < 4; nf++) {
                mma_f16(acc[mf][2*nf],   a[mf], b[nf][0], b[nf][2]);
                mma_f16(acc[mf][2*nf+1], a[mf], b[nf][1], b[nf][3]);
            }
    }
}
__device__ __forceinline__ void g_mainloop(uint32_t sb, const __half* A,
                                           const __half* B, int m0, int n0,
                                           int tid, int wm, int wn,
                                           float acc[4][8][4])
{
#pragma unroll
    for (int i = 0; i < 4; i++)
#pragma unroll
        for (int j = 0; j < 8; j++)
#pragma unroll
            for (int k = 0; k < 4; k++) acc[i][j][k] = 0.f;

    g_issue(sb,           A, B, m0, n0, 0,  tid); CP_COMMIT();
    g_issue(sb + G_STAGE, A, B, m0, n0, 64, tid); CP_COMMIT();

    uint32_t rd = sb, wr = sb + 2 * G_STAGE;
    const uint32_t lim = sb + 3 * G_STAGE;
    for (int c = 0; c < 16; c++) {
        CP_WAIT(1);
        __syncthreads();
        if (c + 2 < 16) {
            g_issue(wr, A, B, m0, n0, (c + 2) * 64, tid);
            wr += G_STAGE; if (wr == lim) wr = sb;
        }
        CP_COMMIT();
        g_mma64(rd, wm, wn, acc);
        rd += G_STAGE; if (rd == lim) rd = sb;
    }
    CP_WAIT(0);
    __syncthreads();
}

// Fused QKV: tiles over [M=8192, N=3072]; seg selects W/bias/output.
__global__ __launch_bounds__(128, 2)
void gemm_qkv(const __half* __restrict__ xf,
              const __half* __restrict__ wq, const __half* __restrict__ wk,
              const __half* __restrict__ wv,
              const float* __restrict__ bq, const float* __restrict__ bk,
              const float* __restrict__ bv,
              __half* __restrict__ qf, __half* __restrict__ kf,
              __half* __restrict__ vf)
{
    extern __shared__ char sm_[];
    const uint32_t sb = smem_u32(sm_);
    const int tid = threadIdx.x;
    const int wid = tid >> 5, lane = tid & 31;
    const int wm = wid & 1, wn = wid >> 1;

    for (int tile = blockIdx.x; tile < 64 * 24; tile += gridDim.x) {
        const int ntile = tile % 24;
        const int m0 = (tile / 24) * 128;
        const int seg = ntile >> 3;
        const int n0 = (ntile & 7) * 128;
        const __half* B = (seg == 0) ? wq : (seg == 1) ? wk : wv;
        const float* bias = (seg == 0) ? bq : (seg == 1) ? bk : bv;
        __half* dst = (seg == 0) ? qf : (seg == 1) ? kf : vf;

        float acc[4][8][4];
        g_mainloop(sb, xf, B, m0, n0, tid, wm, wn, acc);

        const int g = lane >> 2, q = lane & 3;
        const float sc = (seg == 0) ? QSCALE : 1.f;
#pragma unroll
        for (int mf = 0; mf < 4; mf++) {
#pragma unroll
            for (int half = 0; half < 2; half++) {
                const int row = m0 + wm * 64 + mf * 16 + g + half * 8;
#pragma unroll
                for (int nt = 0; nt < 8; nt++) {
                    const int col = n0 + wn * 64 + nt * 8 + q * 2;
                    float2 bi = *(const float2*)(bias + col);
                    float ox = (acc[mf][nt][half * 2]     + bi.x) * sc;
                    float oy = (acc[mf][nt][half * 2 + 1] + bi.y) * sc;
                    size_t off = (((size_t)(row >> 11) * HH + (col >> 6)) * SS
                                  + (row & (SS - 1))) * HDIM + (col & 63);
                    *(uint32_t*)(dst + off) = packh2(ox, oy);
                }
            }
        }
    }
}

// EPI: 2=bias+res->fp32 | 4=bias+relu->f16 rowmajor
template<int EPI>
__global__ __launch_bounds__(128, 2)
void gemm_mma(const __half* __restrict__ A, const __half* __restrict__ B,
              const float* __restrict__ bias, const float* __restrict__ res,
              float* __restrict__ C, __half* __restrict__ Co)
{
    extern __shared__ char sm_[];
    const uint32_t sb = smem_u32(sm_);
    const int tid = threadIdx.x;
    const int wid = tid >> 5, lane = tid & 31;
    const int wm = wid & 1, wn = wid >> 1;

    for (int tile = blockIdx.x; tile < G_TILES; tile += gridDim.x) {
        const int m0 = (tile >> 3) * 128, n0 = (tile & 7) * 128;

        float acc[4][8][4];
        g_mainloop(sb, A, B, m0, n0, tid, wm, wn, acc);

        const int g = lane >> 2, q = lane & 3;
#pragma unroll
        for (int mf = 0; mf < 4; mf++) {
#pragma unroll
            for (int half = 0; half < 2; half++) {
                const int row = m0 + wm * 64 + mf * 16 + g + half * 8;
#pragma unroll
                for (int nt = 0; nt < 8; nt++) {
                    const int col = n0 + wn * 64 + nt * 8 + q * 2;
                    float2 bi = *(const float2*)(bias + col);
                    float ox = acc[mf][nt][half * 2]     + bi.x;
                    float oy = acc[mf][nt][half * 2 + 1] + bi.y;
                    if (EPI == 2) {
                        float2 rv = *(const float2*)(res + (size_t)row * DD + col);
                        *(float2*)(C + (size_t)row * DD + col) =
                            make_float2(ox + rv.x, oy + rv.y);
                    } else {
                        ox = fmaxf(ox, 0.f); oy = fmaxf(oy, 0.f);
                        *(uint32_t*)(Co + (size_t)row * DD + col) = packh2(ox, oy);
                    }
                }
            }
        }
    }
}

// ---------------------------------------------------------------------------
// Flash attention: 4 warps x 32 q-rows, 64-key tiles, 5-stage KV cp.async,
// SOFTWARE-PIPELINED: softmax(kt) -> QK(kt+1) -> PV(kt). The independent
// QK HMMAs fill the MUFU/CVT latency of the softmax chain.
// smem: Q[0,16K) + 5 x 16K stages = 96KB -> 2 CTAs/SM.
// ---------------------------------------------------------------------------
#define AT_STAGE 16384
#define A_SMEM   (16384 + 5 * AT_STAGE)   // 98304
#define NKT (SS / 64)                      // 32
#define A_TILES (BB * HH * (SS / 128))     // 1024

__global__ __launch_bounds__(128, 2)
void attn_mma(const __half* __restrict__ Qf, const __half* __restrict__ Kf,
              const __half* __restrict__ Vf, __half* __restrict__ AVf)
{
    extern __shared__ char sm_[];
    const uint32_t sb = smem_u32(sm_);
    const int tid = threadIdx.x, wid = tid >> 5, lane = tid & 31;
    const uint32_t stage0 = sb + 16384;
    const uint32_t stlim  = stage0 + 5u * AT_STAGE;

    for (int tile = blockIdx.x; tile < A_TILES; tile += gridDim.x) {
        const int qt = tile & 15, bh = tile >> 4;
        const int b = bh >> 4, h = bh & 15;
        const size_t hbase = ((size_t)b * HH + h) * SS;
        const __half* Qb = Qf + (hbase + (size_t)qt * 128) * HDIM;

        // Q tile
#pragma unroll
        for (int it = 0; it < 8; it++) {
            int f = it * 128 + tid; int row = f >> 3, c = f & 7;
            cpa16(sb + swoff(row, c), Qb + row * HDIM + c * 8);
        }
        CP_COMMIT();

        auto issue_kv = [&](uint32_t st, int kt) {
            const size_t tb = (hbase + (size_t)kt * 64) * HDIM;
#pragma unroll
            for (int it = 0; it < 4; it++) {
                int f = it * 128 + tid; int row = f >> 3, c = f & 7;
                uint32_t off = swoff(row, c);
                int ga = row * HDIM + c * 8;
                cpa16(st + off,        Kf + tb + ga);
                cpa16(st + 8192 + off, Vf + tb + ga);
            }
        };
        issue_kv(stage0,                0); CP_COMMIT();
        issue_kv(stage0 +     AT_STAGE, 1); CP_COMMIT();
        issue_kv(stage0 + 2 * AT_STAGE, 2); CP_COMMIT();
        issue_kv(stage0 + 3 * AT_STAGE, 3); CP_COMMIT();

        CP_WAIT(4);      // Q ready
        __syncthreads();

        uint32_t QA[2][4][4];
#pragma unroll
        for (int mf = 0; mf < 2; mf++)
#pragma unroll
            for (int j = 0; j < 4; j++)
                ldsm4(QA[mf][j], frag_addr(sb, wid * 32 + mf * 16, j));

        float oacc[2][8][4];
#pragma unroll
        for (int mf = 0; mf < 2; mf++)
#pragma unroll
            for (int i = 0; i < 8; i++)
#pragma unroll
                for (int j = 0; j < 4; j++) oacc[mf][i][j] = 0.f;
        float lg[2] = {0.f, 0.f}, lg8[2] = {0.f, 0.f};

        // S helper: full QK for a stage into sacc
        auto qk = [&](uint32_t st, float sacc[2][8][4]) {
#pragma unroll
            for (int j = 0; j < 4; j++) {
#pragma unroll
                for (int np = 0; np < 4; np++) {
                    uint32_t kk[4];
                    ldsm4(kk, frag_addr(st, np * 16, j));
#pragma unroll
                    for (int mf = 0; mf < 2; mf++) {
                        if (j == 0) {
                            mma_f16_z(sacc[mf][2*np],   QA[mf][0], kk[0], kk[2]);
                            mma_f16_z(sacc[mf][2*np+1], QA[mf][0], kk[1], kk[3]);
                        } else {
                            mma_f16(sacc[mf][2*np],   QA[mf][j], kk[0], kk[2]);
                            mma_f16(sacc[mf][2*np+1], QA[mf][j], kk[1], kk[3]);
                        }
                    }
                }
            }
        };

        uint32_t st_cur = stage0;                 // stage kt
        uint32_t st_wr  = stage0 + 4u * AT_STAGE; // next issue slot

        // first S
        CP_WAIT(3);
        __syncthreads();
        float sacc[2][8][4];
        qk(st_cur, sacc);

        for (int kt = 0; kt < NKT; kt++) {
            // ---- softmax(kt): P = exp2(sacc), row sums (registers only)
            uint32_t P0[2][8], P1[2][8];
#pragma unroll
            for (int mf = 0; mf < 2; mf++) {
                __half2 a0 = __floats2half2_rn(0.f, 0.f);
                __half2 a1 = a0;
#pragma unroll
                for (int nt = 0; nt < 8; nt++) {
                    P0[mf][nt] = ex2_pack(sacc[mf][nt][0], sacc[mf][nt][1]);
                    P1[mf][nt] = ex2_pack(sacc[mf][nt][2], sacc[mf][nt][3]);
                    a0 = __hadd2(a0, *reinterpret_cast<__half2*>(&P0[mf][nt]));
                    a1 = __hadd2(a1, *reinterpret_cast<__half2*>(&P1[mf][nt]));
                }
                float2 f0 = __half22float2(a0); lg[mf]  += f0.x + f0.y;
                float2 f1 = __half22float2(a1); lg8[mf] += f1.x + f1.y;
            }

            const uint32_t st_v = st_cur + 8192;   // V of tile kt

            // ---- QK(kt+1): independent HMMAs overlap the ex2/cvt latency
            if (kt + 1 < NKT) {
                __syncthreads();                   // all warps done PV(kt-1)
                if (kt + 4 < NKT) {
                    issue_kv(st_wr, kt + 4);       // overwrites slot of stage kt-1
                    st_wr += AT_STAGE; if (st_wr == stlim) st_wr = stage0;
                }
                CP_COMMIT();
                CP_WAIT(3);                        // stage kt+1 complete
                __syncthreads();                   // ... and visible to all
                st_cur += AT_STAGE; if (st_cur == stlim) st_cur = stage0;
                qk(st_cur, sacc);
            }

            // ---- PV(kt)
#pragma unroll
            for (int j2 = 0; j2 < 4; j2++) {
#pragma unroll
                for (int np = 0; np < 4; np++) {
                    uint32_t vv[4];
                    ldsm4t(vv, fragV_addr(st_v, j2 * 16, np));
#pragma unroll
                    for (int mf = 0; mf < 2; mf++) {
                        uint32_t ap[4] = {P0[mf][2*j2], P1[mf][2*j2],
                                          P0[mf][2*j2+1], P1[mf][2*j2+1]};
                        mma_f16(oacc[mf][2*np],   ap, vv[0], vv[2]);
                        mma_f16(oacc[mf][2*np+1], ap, vv[1], vv[3]);
                    }
                }
            }
        }

#pragma unroll
        for (int mf = 0; mf < 2; mf++) {
            lg[mf]  += __shfl_xor_sync(0xffffffffu, lg[mf], 1);
            lg[mf]  += __shfl_xor_sync(0xffffffffu, lg[mf], 2);
            lg8[mf] += __shfl_xor_sync(0xffffffffu, lg8[mf], 1);
            lg8[mf] += __shfl_xor_sync(0xffffffffu, lg8[mf], 2);
        }

        const int g = lane >> 2, q = lane & 3;
#pragma unroll
        for (int mf = 0; mf < 2; mf++) {
            const float inv = 1.f / lg[mf], inv8 = 1.f / lg8[mf];
            const size_t row = (size_t)b * SS + (size_t)qt * 128
                               + wid * 32 + mf * 16 + g;
            const size_t o0 = row * DD + h * HDIM;
            const size_t o1 = (row + 8) * DD + h * HDIM;
#pragma unroll
            for (int nt = 0; nt < 8; nt++) {
                const int col = nt * 8 + q * 2;
                *(uint32_t*)(AVf + o0 + col) =
                    packh2(oacc[mf][nt][0] * inv,  oacc[mf][nt][1] * inv);
                *(uint32_t*)(AVf + o1 + col) =
                    packh2(oacc[mf][nt][2] * inv8, oacc[mf][nt][3] * inv8);
            }
        }
        CP_WAIT(0);
        __syncthreads();
    }
}

// ---------------------------------------------------------------------------
// LayerNorm; optionally also emits f16 copy of the output
// ---------------------------------------------------------------------------
template<bool EMIT16>
__global__ __launch_bounds__(256)
void ln_kernel(const float* __restrict__ X, const float* __restrict__ scale,
               const float* __restrict__ bias, float* __restrict__ Y,
               __half* __restrict__ Yf)
{
    __shared__ float red[2][8];
    const int row = blockIdx.x;
    const int tid = threadIdx.x;
    const float4 v = *(const float4*)(X + (size_t)row * DD + tid * 4);
    float s = v.x + v.y + v.z + v.w;
    float qq = v.x * v.x + v.y * v.y + v.z * v.z + v.w * v.w;
#pragma unroll
    for (int w = 16; w >= 1; w >>= 1) {
        s  += __shfl_xor_sync(0xffffffffu, s, w);
        qq += __shfl_xor_sync(0xffffffffu, qq, w);
    }
    if ((tid & 31) == 0) { red[0][tid >> 5] = s; red[1][tid >> 5] = qq; }
    __syncthreads();
    float st = 0.f, qt = 0.f;
#pragma unroll
    for (int i = 0; i < 8; i++) { st += red[0][i]; qt += red[1][i]; }
    const float mean = st * (1.f / DD);
    const float var  = qt * (1.f / DD) - mean * mean;
    const float rs   = rsqrtf(var + 1e-6f);
    const float4 sc = *(const float4*)(scale + tid * 4);
    const float4 bi = *(const float4*)(bias + tid * 4);
    float4 oy;
    oy.x = (v.x - mean) * rs * sc.x + bi.x;
    oy.y = (v.y - mean) * rs * sc.y + bi.y;
    oy.z = (v.z - mean) * rs * sc.z + bi.z;
    oy.w = (v.w - mean) * rs * sc.w + bi.w;
    *(float4*)(Y + (size_t)row * DD + tid * 4) = oy;
    if (EMIT16) {
        size_t off = (size_t)row * DD + tid * 4;
        *(uint2*)(Yf + off) = make_uint2(packh2(oy.x, oy.y), packh2(oy.z, oy.w));
    }
}

// ---------------------------------------------------------------------------
// Launch
// ---------------------------------------------------------------------------
extern "C" void kernel_launch(void* const* d_in, const int* in_sizes, int n_in,
                              void* d_out, int out_size)
{
    (void)in_sizes; (void)n_in; (void)out_size;
    const float* x  = (const float*)d_in[0];
    const float* Wq = (const float*)d_in[3];
    const float* bq = (const float*)d_in[4];
    const float* Wk = (const float*)d_in[5];
    const float* bk = (const float*)d_in[6];
    const float* Wv = (const float*)d_in[7];
    const float* bv = (const float*)d_in[8];
    const float* Wo = (const float*)d_in[9];
    const float* bo = (const float*)d_in[10];
    const float* W1 = (const float*)d_in[11];
    const float* b1 = (const float*)d_in[12];
    const float* W2 = (const float*)d_in[13];
    const float* b2 = (const float*)d_in[14];
    const float* ln1s = (const float*)d_in[15];
    const float* ln1b = (const float*)d_in[16];
    const float* ln2s = (const float*)d_in[17];
    const float* ln2b = (const float*)d_in[18];
    float* out = (float*)d_out;

    float *Tb, *Hb;
    cudaGetSymbolAddress((void**)&Tb, g_T);
    cudaGetSymbolAddress((void**)&Hb, g_H);

    __half *xf, *qf, *kf, *vf, *avf, *hf, *ff;
    cudaGetSymbolAddress((void**)&xf,  g_xf);
    cudaGetSymbolAddress((void**)&qf,  g_Qf);
    cudaGetSymbolAddress((void**)&kf,  g_Kf);
    cudaGetSymbolAddress((void**)&vf,  g_Vf);
    cudaGetSymbolAddress((void**)&avf, g_AVf);
    cudaGetSymbolAddress((void**)&hf,  g_Hf);
    cudaGetSymbolAddress((void**)&ff,  g_Ff);

    __half *wq, *wk, *wv, *wo, *w1, *w2;
    cudaGetSymbolAddress((void**)&wq, g_Wq); cudaGetSymbolAddress((void**)&wk, g_Wk);
    cudaGetSymbolAddress((void**)&wv, g_Wv); cudaGetSymbolAddress((void**)&wo, g_Wo);
    cudaGetSymbolAddress((void**)&w1, g_W1); cudaGetSymbolAddress((void**)&w2, g_W2);

    cudaFuncSetAttribute(gemm_qkv,    cudaFuncAttributeMaxDynamicSharedMemorySize, G_SMEM);
    cudaFuncSetAttribute(gemm_mma<2>, cudaFuncAttributeMaxDynamicSharedMemorySize, G_SMEM);
    cudaFuncSetAttribute(gemm_mma<4>, cudaFuncAttributeMaxDynamicSharedMemorySize, G_SMEM);
    cudaFuncSetAttribute(attn_mma,    cudaFuncAttributeMaxDynamicSharedMemorySize, A_SMEM);

    // weight transposes (one launch), x convert
    wsplit_all<<<dim3(32, 32, 6), 256>>>(Wq, Wk, Wv, Wo, W1, W2,
                                         wq, wk, wv, wo, w1, w2);
    xcvt_kernel<<<MROWS * DD / 1024, 256>>>(x, xf);

    // Fused QKV projection (persistent)
    gemm_qkv<<<NSM_CTAS, 128, G_SMEM>>>(xf, wq, wk, wv, bq, bk, bv, qf, kf, vf);

    // Attention
    attn_mma<<<NSM_CTAS, 128, A_SMEM>>>(qf, kf, vf, avf);

    // Wo + residual(x) -> T; LN1 -> H (fp32 + f16)
    gemm_mma<2><<<NSM_CTAS, 128, G_SMEM>>>(avf, wo, bo, x, Tb, nullptr);
    ln_kernel<true><<<MROWS, 256>>>(Tb, ln1s, ln1b, Hb, hf);

    // FFN
    gemm_mma<4><<<NSM_CTAS, 128, G_SMEM>>>(hf, w1, b1, nullptr, nullptr, ff);
    gemm_mma<2><<<NSM_CTAS, 128, G_SMEM>>>(ff, w2, b2, Hb, Tb, nullptr);
    ln_kernel<false><<<MROWS, 256>>>(Tb, ln2s, ln2b, out, nullptr);
}

// round 14
// speedup vs baseline: 1.0215x; 1.0215x over previous
#include <cuda_runtime.h>
#include <cuda_bf16.h>
#include <cuda_fp16.h>
#include <cstdint>

#define BB 4
#define SS 2048
#define DD 1024
#define HH 16
#define HDIM 64
#define MROWS (BB*SS)   // 8192
#define QSCALE 0.1803368801111204f   // log2(e)/8
#define NSM_CTAS 296    // 148 SMs * 2 CTAs

// ---------------------------------------------------------------------------
// Scratch (device globals; allocation-free)
// ---------------------------------------------------------------------------
__device__ __align__(128) float g_T[MROWS*DD];
__device__ __align__(128) float g_H[MROWS*DD];

__device__ __align__(128) __half g_xf[MROWS*DD];
__device__ __align__(128) __half g_Qf[MROWS*DD];   // head-major, pre-scaled
__device__ __align__(128) __half g_Kf[MROWS*DD];   // head-major
__device__ __align__(128) __half g_Vf[MROWS*DD];   // head-major
__device__ __align__(128) __half g_AVf[MROWS*DD];
__device__ __align__(128) __half g_Hf[MROWS*DD];
__device__ __align__(128) __half g_Ff[MROWS*DD];

__device__ __align__(128) __half g_Wq[DD*DD];
__device__ __align__(128) __half g_Wk[DD*DD];
__device__ __align__(128) __half g_Wv[DD*DD];
__device__ __align__(128) __half g_Wo[DD*DD];
__device__ __align__(128) __half g_W1[DD*DD];
__device__ __align__(128) __half g_W2[DD*DD];

// ---------------------------------------------------------------------------
// Helpers
// ---------------------------------------------------------------------------
__device__ __forceinline__ uint32_t smem_u32(const void* p) {
    uint32_t a;
    asm("{ .reg .u64 t; cvta.to.shared.u64 t, %1; cvt.u32.u64 %0, t; }"
        : "=r"(a) : "l"(p));
    return a;
}
__device__ __forceinline__ void cpa16(uint32_t saddr, const void* g) {
    asm volatile("cp.async.cg.shared.global [%0], [%1], 16;"
                 :: "r"(saddr), "l"(g) : "memory");
}
#define CP_COMMIT() asm volatile("cp.async.commit_group;" ::: "memory")
#define CP_WAIT(n)  asm volatile("cp.async.wait_group %0;" :: "n"(n) : "memory")

__device__ __forceinline__ void ldsm4(uint32_t* r, uint32_t a) {
    asm volatile("ldmatrix.sync.aligned.m8n8.x4.shared.b16 {%0,%1,%2,%3}, [%4];"
        : "=r"(r[0]), "=r"(r[1]), "=r"(r[2]), "=r"(r[3]) : "r"(a));
}
__device__ __forceinline__ void ldsm4t(uint32_t* r, uint32_t a) {
    asm volatile("ldmatrix.sync.aligned.m8n8.x4.trans.shared.b16 {%0,%1,%2,%3}, [%4];"
        : "=r"(r[0]), "=r"(r[1]), "=r"(r[2]), "=r"(r[3]) : "r"(a));
}
__device__ __forceinline__ void mma_f16(float* c, const uint32_t* a,
                                        uint32_t b0, uint32_t b1) {
    asm volatile("mma.sync.aligned.m16n8k16.row.col.f32.f16.f16.f32 "
        "{%0,%1,%2,%3}, {%4,%5,%6,%7}, {%8,%9}, {%0,%1,%2,%3};"
        : "+f"(c[0]), "+f"(c[1]), "+f"(c[2]), "+f"(c[3])
        : "r"(a[0]), "r"(a[1]), "r"(a[2]), "r"(a[3]), "r"(b0), "r"(b1));
}
// d = a*b + 0
__device__ __forceinline__ void mma_f16_z(float* d, const uint32_t* a,
                                          uint32_t b0, uint32_t b1) {
    asm volatile("mma.sync.aligned.m16n8k16.row.col.f32.f16.f16.f32 "
        "{%0,%1,%2,%3}, {%4,%5,%6,%7}, {%8,%9}, {%10,%10,%10,%10};"
        : "=f"(d[0]), "=f"(d[1]), "=f"(d[2]), "=f"(d[3])
        : "r"(a[0]), "r"(a[1]), "r"(a[2]), "r"(a[3]), "r"(b0), "r"(b1),
          "f"(0.f));
}
// 128B-row XOR swizzle (64 f16 per row, 8 chunks of 16B)
__device__ __forceinline__ uint32_t swoff(int row, int chunk) {
    return (uint32_t)(row * 128 + ((chunk ^ (row & 7)) << 4));
}
__device__ __forceinline__ uint32_t frag_addr(uint32_t base, int r0, int kstep) {
    int lane = threadIdx.x & 31;
    int row = r0 + (lane & 15);
    int chunk = kstep * 2 + (lane >> 4);
    return base + swoff(row, chunk);
}
__device__ __forceinline__ uint32_t fragV_addr(uint32_t base, int kb, int dpair) {
    int lane = threadIdx.x & 31;
    int row = kb + (lane & 7) + ((lane & 16) >> 1);
    int chunk = dpair * 2 + ((lane >> 3) & 1);
    return base + swoff(row, chunk);
}
__device__ __forceinline__ uint32_t packh2(float a, float b) {
    __half2 t = __floats2half2_rn(a, b);
    return *reinterpret_cast<uint32_t*>(&t);
}
__device__ __forceinline__ uint32_t ex2_pack(float a, float b) {
    __half2 hx = __floats2half2_rn(a, b);
    uint32_t u = *reinterpret_cast<uint32_t*>(&hx);
    asm("ex2.approx.f16x2 %0, %0;" : "+r"(u));
    return u;
}

// ---------------------------------------------------------------------------
// Batched weight prep: 6 weights [K,N] fp32 -> [N,K] f16, one launch
// ---------------------------------------------------------------------------
__global__ __launch_bounds__(256)
void wsplit_all(const float* __restrict__ W0, const float* __restrict__ W1,
                const float* __restrict__ W2, const float* __restrict__ W3,
                const float* __restrict__ W4, const float* __restrict__ W5,
                __half* __restrict__ T0, __half* __restrict__ T1,
                __half* __restrict__ T2, __half* __restrict__ T3,
                __half* __restrict__ T4, __half* __restrict__ T5)
{
    const float* W; __half* T;
    switch (blockIdx.z) {
        case 0: W = W0; T = T0; break;
        case 1: W = W1; T = T1; break;
        case 2: W = W2; T = T2; break;
        case 3: W = W3; T = T3; break;
        case 4: W = W4; T = T4; break;
        default: W = W5; T = T5; break;
    }
    __shared__ float tile[32][33];
    const int bn = blockIdx.x * 32;
    const int bk = blockIdx.y * 32;
    const int tx = threadIdx.x & 31, ty = threadIdx.x >> 5;
#pragma unroll
    for (int i = ty; i < 32; i += 8)
        tile[i][tx] = W[(size_t)(bk + i) * DD + bn + tx];
    __syncthreads();
#pragma unroll
    for (int i = ty; i < 32; i += 8)
        T[(size_t)(bn + i) * DD + bk + tx] = __float2half_rn(tile[tx][i]);
}

// fp32 -> f16 convert (layout-preserving)
__global__ __launch_bounds__(256)
void xcvt_kernel(const float* __restrict__ X, __half* __restrict__ Xf)
{
    size_t i = ((size_t)blockIdx.x * 256 + threadIdx.x) * 4;
    float4 v = *(const float4*)(X + i);
    *(uint2*)(Xf + i) = make_uint2(packh2(v.x, v.y), packh2(v.z, v.w));
}

// ---------------------------------------------------------------------------
// Dense GEMM core: 128 threads = 4 warps (2m x 2n), warp tile 64x64,
// CTA 128x128, k-chunk 64, 3-stage cp.async (32KB/stage, cyclic ptrs).
// ---------------------------------------------------------------------------
#define G_STAGE 32768
#define G_SMEM  (3 * G_STAGE)   // 98304
#define G_TILES 512             // 64 m-tiles * 8 n-tiles

__device__ __forceinline__ void g_issue(uint32_t st,
    const __half* A, const __half* B, int m0, int n0, int kc0, int tid)
{
#pragma unroll
    for (int it = 0; it < 8; it++) {
        int f = it * 128 + tid;
        int row = f >> 3, c = f & 7;
        uint32_t off = swoff(row, c);
        cpa16(st + off,         A + (size_t)(m0 + row) * DD + kc0 + c * 8);
        cpa16(st + 16384 + off, B + (size_t)(n0 + row) * DD + kc0 + c * 8);
    }
}
__device__ __forceinline__ void g_mma64(uint32_t base, int wm, int wn,
                                        float acc[4][8][4])
{
#pragma unroll
    for (int j = 0; j < 4; j++) {
        uint32_t a[4][4], b[4][4];
#pragma unroll
        for (int i = 0; i < 4; i++)
            ldsm4(a[i], frag_addr(base, wm * 64 + i * 16, j));
#pragma unroll
        for (int i = 0; i < 4; i++)
            ldsm4(b[i], frag_addr(base + 16384, wn * 64 + i * 16, j));
#pragma unroll
        for (int mf = 0; mf < 4; mf++)
#pragma unroll
            for (int nf = 0; nf < 4; nf++) {
                mma_f16(acc[mf][2*nf],   a[mf], b[nf][0], b[nf][2]);
                mma_f16(acc[mf][2*nf+1], a[mf], b[nf][1], b[nf][3]);
            }
    }
}
__device__ __forceinline__ void g_mainloop(uint32_t sb, const __half* A,
                                           const __half* B, int m0, int n0,
                                           int tid, int wm, int wn,
                                           float acc[4][8][4])
{
#pragma unroll
    for (int i = 0; i < 4; i++)
#pragma unroll
        for (int j = 0; j < 8; j++)
#pragma unroll
            for (int k = 0; k < 4; k++) acc[i][j][k] = 0.f;

    g_issue(sb,           A, B, m0, n0, 0,  tid); CP_COMMIT();
    g_issue(sb + G_STAGE, A, B, m0, n0, 64, tid); CP_COMMIT();

    uint32_t rd = sb, wr = sb + 2 * G_STAGE;
    const uint32_t lim = sb + 3 * G_STAGE;
    for (int c = 0; c < 16; c++) {
        CP_WAIT(1);
        __syncthreads();
        if (c + 2 < 16) {
            g_issue(wr, A, B, m0, n0, (c + 2) * 64, tid);
            wr += G_STAGE; if (wr == lim) wr = sb;
        }
        CP_COMMIT();
        g_mma64(rd, wm, wn, acc);
        rd += G_STAGE; if (rd == lim) rd = sb;
    }
    CP_WAIT(0);
    __syncthreads();
}

// Fused QKV: tiles over [M=8192, N=3072]; seg selects W/bias/output.
__global__ __launch_bounds__(128, 2)
void gemm_qkv(const __half* __restrict__ xf,
              const __half* __restrict__ wq, const __half* __restrict__ wk,
              const __half* __restrict__ wv,
              const float* __restrict__ bq, const float* __restrict__ bk,
              const float* __restrict__ bv,
              __half* __restrict__ qf, __half* __restrict__ kf,
              __half* __restrict__ vf)
{
    extern __shared__ char sm_[];
    const uint32_t sb = smem_u32(sm_);
    const int tid = threadIdx.x;
    const int wid = tid >> 5, lane = tid & 31;
    const int wm = wid & 1, wn = wid >> 1;

    for (int tile = blockIdx.x; tile < 64 * 24; tile += gridDim.x) {
        const int ntile = tile % 24;
        const int m0 = (tile / 24) * 128;
        const int seg = ntile >> 3;
        const int n0 = (ntile & 7) * 128;
        const __half* B = (seg == 0) ? wq : (seg == 1) ? wk : wv;
        const float* bias = (seg == 0) ? bq : (seg == 1) ? bk : bv;
        __half* dst = (seg == 0) ? qf : (seg == 1) ? kf : vf;

        float acc[4][8][4];
        g_mainloop(sb, xf, B, m0, n0, tid, wm, wn, acc);

        const int g = lane >> 2, q = lane & 3;
        const float sc = (seg == 0) ? QSCALE : 1.f;
#pragma unroll
        for (int mf = 0; mf < 4; mf++) {
#pragma unroll
            for (int half = 0; half < 2; half++) {
                const int row = m0 + wm * 64 + mf * 16 + g + half * 8;
#pragma unroll
                for (int nt = 0; nt < 8; nt++) {
                    const int col = n0 + wn * 64 + nt * 8 + q * 2;
                    float2 bi = *(const float2*)(bias + col);
                    float ox = (acc[mf][nt][half * 2]     + bi.x) * sc;
                    float oy = (acc[mf][nt][half * 2 + 1] + bi.y) * sc;
                    size_t off = (((size_t)(row >> 11) * HH + (col >> 6)) * SS
                                  + (row & (SS - 1))) * HDIM + (col & 63);
                    *(uint32_t*)(dst + off) = packh2(ox, oy);
                }
            }
        }
    }
}

// EPI: 2=bias+res->fp32 | 4=bias+relu->f16 rowmajor
template<int EPI>
__global__ __launch_bounds__(128, 2)
void gemm_mma(const __half* __restrict__ A, const __half* __restrict__ B,
              const float* __restrict__ bias, const float* __restrict__ res,
              float* __restrict__ C, __half* __restrict__ Co)
{
    extern __shared__ char sm_[];
    const uint32_t sb = smem_u32(sm_);
    const int tid = threadIdx.x;
    const int wid = tid >> 5, lane = tid & 31;
    const int wm = wid & 1, wn = wid >> 1;

    for (int tile = blockIdx.x; tile < G_TILES; tile += gridDim.x) {
        const int m0 = (tile >> 3) * 128, n0 = (tile & 7) * 128;

        float acc[4][8][4];
        g_mainloop(sb, A, B, m0, n0, tid, wm, wn, acc);

        const int g = lane >> 2, q = lane & 3;
#pragma unroll
        for (int mf = 0; mf < 4; mf++) {
#pragma unroll
            for (int half = 0; half < 2; half++) {
                const int row = m0 + wm * 64 + mf * 16 + g + half * 8;
#pragma unroll
                for (int nt = 0; nt < 8; nt++) {
                    const int col = n0 + wn * 64 + nt * 8 + q * 2;
                    float2 bi = *(const float2*)(bias + col);
                    float ox = acc[mf][nt][half * 2]     + bi.x;
                    float oy = acc[mf][nt][half * 2 + 1] + bi.y;
                    if (EPI == 2) {
                        float2 rv = *(const float2*)(res + (size_t)row * DD + col);
                        *(float2*)(C + (size_t)row * DD + col) =
                            make_float2(ox + rv.x, oy + rv.y);
                    } else {
                        ox = fmaxf(ox, 0.f); oy = fmaxf(oy, 0.f);
                        *(uint32_t*)(Co + (size_t)row * DD + col) = packh2(ox, oy);
                    }
                }
            }
        }
    }
}

// ---------------------------------------------------------------------------
// Flash attention: 4 warps x 32 q-rows, 64-key tiles, 5-stage KV cp.async,
// single barrier/iter. QK and softmax FUSED at 16-key (np) granularity:
// each np's ex2/cvt chain overlaps the next np's independent LDSM+HMMA.
// sacc live range = 16 floats (was 64) -> off the 255-reg ceiling.
// smem: Q[0,16K) + 5 x 16K stages = 96KB -> 2 CTAs/SM.
// ---------------------------------------------------------------------------
#define AT_STAGE 16384
#define A_SMEM   (16384 + 5 * AT_STAGE)   // 98304
#define NKT (SS / 64)                      // 32
#define A_TILES (BB * HH * (SS / 128))     // 1024

__global__ __launch_bounds__(128, 2)
void attn_mma(const __half* __restrict__ Qf, const __half* __restrict__ Kf,
              const __half* __restrict__ Vf, __half* __restrict__ AVf)
{
    extern __shared__ char sm_[];
    const uint32_t sb = smem_u32(sm_);
    const int tid = threadIdx.x, wid = tid >> 5, lane = tid & 31;
    const uint32_t stage0 = sb + 16384;
    const uint32_t stlim  = stage0 + 5u * AT_STAGE;

    for (int tile = blockIdx.x; tile < A_TILES; tile += gridDim.x) {
        const int qt = tile & 15, bh = tile >> 4;
        const int b = bh >> 4, h = bh & 15;
        const size_t hbase = ((size_t)b * HH + h) * SS;
        const __half* Qb = Qf + (hbase + (size_t)qt * 128) * HDIM;

        // Q tile
#pragma unroll
        for (int it = 0; it < 8; it++) {
            int f = it * 128 + tid; int row = f >> 3, c = f & 7;
            cpa16(sb + swoff(row, c), Qb + row * HDIM + c * 8);
        }
        CP_COMMIT();

        auto issue_kv = [&](uint32_t st, int kt) {
            const size_t tb = (hbase + (size_t)kt * 64) * HDIM;
#pragma unroll
            for (int it = 0; it < 4; it++) {
                int f = it * 128 + tid; int row = f >> 3, c = f & 7;
                uint32_t off = swoff(row, c);
                int ga = row * HDIM + c * 8;
                cpa16(st + off,        Kf + tb + ga);
                cpa16(st + 8192 + off, Vf + tb + ga);
            }
        };
        issue_kv(stage0,                0); CP_COMMIT();
        issue_kv(stage0 +     AT_STAGE, 1); CP_COMMIT();
        issue_kv(stage0 + 2 * AT_STAGE, 2); CP_COMMIT();
        issue_kv(stage0 + 3 * AT_STAGE, 3); CP_COMMIT();

        CP_WAIT(4);      // Q ready
        __syncthreads();

        uint32_t QA[2][4][4];
#pragma unroll
        for (int mf = 0; mf < 2; mf++)
#pragma unroll
            for (int j = 0; j < 4; j++)
                ldsm4(QA[mf][j], frag_addr(sb, wid * 32 + mf * 16, j));

        float oacc[2][8][4];
#pragma unroll
        for (int mf = 0; mf < 2; mf++)
#pragma unroll
            for (int i = 0; i < 8; i++)
#pragma unroll
                for (int j = 0; j < 4; j++) oacc[mf][i][j] = 0.f;
        float lg[2] = {0.f, 0.f}, lg8[2] = {0.f, 0.f};

        uint32_t st_cur = stage0;
        uint32_t st_wr  = stage0 + 4u * AT_STAGE;

        for (int kt = 0; kt < NKT; kt++) {
            CP_WAIT(3);
            __syncthreads();
            if (kt + 4 < NKT) {
                issue_kv(st_wr, kt + 4);
                st_wr += AT_STAGE; if (st_wr == stlim) st_wr = stage0;
            }
            CP_COMMIT();

            // ---- fused QK + softmax, per 16-key group (np) ----
            uint32_t P0[2][8], P1[2][8];
            __half2 a0[2], a1[2];
            a0[0] = __floats2half2_rn(0.f, 0.f); a1[0] = a0[0];
            a0[1] = a0[0]; a1[1] = a0[0];
#pragma unroll
            for (int np = 0; np < 4; np++) {
                float sl[2][2][4];
#pragma unroll
                for (int j = 0; j < 4; j++) {
                    uint32_t kk[4];
                    ldsm4(kk, frag_addr(st_cur, np * 16, j));
#pragma unroll
                    for (int mf = 0; mf < 2; mf++) {
                        if (j == 0) {
                            mma_f16_z(sl[mf][0], QA[mf][0], kk[0], kk[2]);
                            mma_f16_z(sl[mf][1], QA[mf][0], kk[1], kk[3]);
                        } else {
                            mma_f16(sl[mf][0], QA[mf][j], kk[0], kk[2]);
                            mma_f16(sl[mf][1], QA[mf][j], kk[1], kk[3]);
                        }
                    }
                }
#pragma unroll
                for (int mf = 0; mf < 2; mf++) {
                    P0[mf][2*np]   = ex2_pack(sl[mf][0][0], sl[mf][0][1]);
                    P1[mf][2*np]   = ex2_pack(sl[mf][0][2], sl[mf][0][3]);
                    P0[mf][2*np+1] = ex2_pack(sl[mf][1][0], sl[mf][1][1]);
                    P1[mf][2*np+1] = ex2_pack(sl[mf][1][2], sl[mf][1][3]);
                    a0[mf] = __hadd2(a0[mf], *reinterpret_cast<__half2*>(&P0[mf][2*np]));
                    a1[mf] = __hadd2(a1[mf], *reinterpret_cast<__half2*>(&P1[mf][2*np]));
                    a0[mf] = __hadd2(a0[mf], *reinterpret_cast<__half2*>(&P0[mf][2*np+1]));
                    a1[mf] = __hadd2(a1[mf], *reinterpret_cast<__half2*>(&P1[mf][2*np+1]));
                }
            }
#pragma unroll
            for (int mf = 0; mf < 2; mf++) {
                float2 f0 = __half22float2(a0[mf]); lg[mf]  += f0.x + f0.y;
                float2 f1 = __half22float2(a1[mf]); lg8[mf] += f1.x + f1.y;
            }

            // ---- PV(kt) ----
            const uint32_t st_v = st_cur + 8192;
#pragma unroll
            for (int j2 = 0; j2 < 4; j2++) {
#pragma unroll
                for (int np = 0; np < 4; np++) {
                    uint32_t vv[4];
                    ldsm4t(vv, fragV_addr(st_v, j2 * 16, np));
#pragma unroll
                    for (int mf = 0; mf < 2; mf++) {
                        uint32_t ap[4] = {P0[mf][2*j2], P1[mf][2*j2],
                                          P0[mf][2*j2+1], P1[mf][2*j2+1]};
                        mma_f16(oacc[mf][2*np],   ap, vv[0], vv[2]);
                        mma_f16(oacc[mf][2*np+1], ap, vv[1], vv[3]);
                    }
                }
            }
            st_cur += AT_STAGE; if (st_cur == stlim) st_cur = stage0;
        }

#pragma unroll
        for (int mf = 0; mf < 2; mf++) {
            lg[mf]  += __shfl_xor_sync(0xffffffffu, lg[mf], 1);
            lg[mf]  += __shfl_xor_sync(0xffffffffu, lg[mf], 2);
            lg8[mf] += __shfl_xor_sync(0xffffffffu, lg8[mf], 1);
            lg8[mf] += __shfl_xor_sync(0xffffffffu, lg8[mf], 2);
        }

        const int g = lane >> 2, q = lane & 3;
#pragma unroll
        for (int mf = 0; mf < 2; mf++) {
            const float inv = 1.f / lg[mf], inv8 = 1.f / lg8[mf];
            const size_t row = (size_t)b * SS + (size_t)qt * 128
                               + wid * 32 + mf * 16 + g;
            const size_t o0 = row * DD + h * HDIM;
            const size_t o1 = (row + 8) * DD + h * HDIM;
#pragma unroll
            for (int nt = 0; nt < 8; nt++) {
                const int col = nt * 8 + q * 2;
                *(uint32_t*)(AVf + o0 + col) =
                    packh2(oacc[mf][nt][0] * inv,  oacc[mf][nt][1] * inv);
                *(uint32_t*)(AVf + o1 + col) =
                    packh2(oacc[mf][nt][2] * inv8, oacc[mf][nt][3] * inv8);
            }
        }
        CP_WAIT(0);
        __syncthreads();
    }
}

// ---------------------------------------------------------------------------
// LayerNorm; optionally also emits f16 copy of the output
// ---------------------------------------------------------------------------
template<bool EMIT16>
__global__ __launch_bounds__(256)
void ln_kernel(const float* __restrict__ X, const float* __restrict__ scale,
               const float* __restrict__ bias, float* __restrict__ Y,
               __half* __restrict__ Yf)
{
    __shared__ float red[2][8];
    const int row = blockIdx.x;
    const int tid = threadIdx.x;
    const float4 v = *(const float4*)(X + (size_t)row * DD + tid * 4);
    float s = v.x + v.y + v.z + v.w;
    float qq = v.x * v.x + v.y * v.y + v.z * v.z + v.w * v.w;
#pragma unroll
    for (int w = 16; w >= 1; w >>= 1) {
        s  += __shfl_xor_sync(0xffffffffu, s, w);
        qq += __shfl_xor_sync(0xffffffffu, qq, w);
    }
    if ((tid & 31) == 0) { red[0][tid >> 5] = s; red[1][tid >> 5] = qq; }
    __syncthreads();
    float st = 0.f, qt = 0.f;
#pragma unroll
    for (int i = 0; i < 8; i++) { st += red[0][i]; qt += red[1][i]; }
    const float mean = st * (1.f / DD);
    const float var  = qt * (1.f / DD) - mean * mean;
    const float rs   = rsqrtf(var + 1e-6f);
    const float4 sc = *(const float4*)(scale + tid * 4);
    const float4 bi = *(const float4*)(bias + tid * 4);
    float4 oy;
    oy.x = (v.x - mean) * rs * sc.x + bi.x;
    oy.y = (v.y - mean) * rs * sc.y + bi.y;
    oy.z = (v.z - mean) * rs * sc.z + bi.z;
    oy.w = (v.w - mean) * rs * sc.w + bi.w;
    *(float4*)(Y + (size_t)row * DD + tid * 4) = oy;
    if (EMIT16) {
        size_t off = (size_t)row * DD + tid * 4;
        *(uint2*)(Yf + off) = make_uint2(packh2(oy.x, oy.y), packh2(oy.z, oy.w));
    }
}

// ---------------------------------------------------------------------------
// Launch
// ---------------------------------------------------------------------------
extern "C" void kernel_launch(void* const* d_in, const int* in_sizes, int n_in,
                              void* d_out, int out_size)
{
    (void)in_sizes; (void)n_in; (void)out_size;
    const float* x  = (const float*)d_in[0];
    const float* Wq = (const float*)d_in[3];
    const float* bq = (const float*)d_in[4];
    const float* Wk = (const float*)d_in[5];
    const float* bk = (const float*)d_in[6];
    const float* Wv = (const float*)d_in[7];
    const float* bv = (const float*)d_in[8];
    const float* Wo = (const float*)d_in[9];
    const float* bo = (const float*)d_in[10];
    const float* W1 = (const float*)d_in[11];
    const float* b1 = (const float*)d_in[12];
    const float* W2 = (const float*)d_in[13];
    const float* b2 = (const float*)d_in[14];
    const float* ln1s = (const float*)d_in[15];
    const float* ln1b = (const float*)d_in[16];
    const float* ln2s = (const float*)d_in[17];
    const float* ln2b = (const float*)d_in[18];
    float* out = (float*)d_out;

    float *Tb, *Hb;
    cudaGetSymbolAddress((void**)&Tb, g_T);
    cudaGetSymbolAddress((void**)&Hb, g_H);

    __half *xf, *qf, *kf, *vf, *avf, *hf, *ff;
    cudaGetSymbolAddress((void**)&xf,  g_xf);
    cudaGetSymbolAddress((void**)&qf,  g_Qf);
    cudaGetSymbolAddress((void**)&kf,  g_Kf);
    cudaGetSymbolAddress((void**)&vf,  g_Vf);
    cudaGetSymbolAddress((void**)&avf, g_AVf);
    cudaGetSymbolAddress((void**)&hf,  g_Hf);
    cudaGetSymbolAddress((void**)&ff,  g_Ff);

    __half *wq, *wk, *wv, *wo, *w1, *w2;
    cudaGetSymbolAddress((void**)&wq, g_Wq); cudaGetSymbolAddress((void**)&wk, g_Wk);
    cudaGetSymbolAddress((void**)&wv, g_Wv); cudaGetSymbolAddress((void**)&wo, g_Wo);
    cudaGetSymbolAddress((void**)&w1, g_W1); cudaGetSymbolAddress((void**)&w2, g_W2);

    cudaFuncSetAttribute(gemm_qkv,    cudaFuncAttributeMaxDynamicSharedMemorySize, G_SMEM);
    cudaFuncSetAttribute(gemm_mma<2>, cudaFuncAttributeMaxDynamicSharedMemorySize, G_SMEM);
    cudaFuncSetAttribute(gemm_mma<4>, cudaFuncAttributeMaxDynamicSharedMemorySize, G_SMEM);
    cudaFuncSetAttribute(attn_mma,    cudaFuncAttributeMaxDynamicSharedMemorySize, A_SMEM);

    // weight transposes (one launch), x convert
    wsplit_all<<<dim3(32, 32, 6), 256>>>(Wq, Wk, Wv, Wo, W1, W2,
                                         wq, wk, wv, wo, w1, w2);
    xcvt_kernel<<<MROWS * DD / 1024, 256>>>(x, xf);

    // Fused QKV projection (persistent)
    gemm_qkv<<<NSM_CTAS, 128, G_SMEM>>>(xf, wq, wk, wv, bq, bk, bv, qf, kf, vf);

    // Attention
    attn_mma<<<NSM_CTAS, 128, A_SMEM>>>(qf, kf, vf, avf);

    // Wo + residual(x) -> T; LN1 -> H (fp32 + f16)
    gemm_mma<2><<<NSM_CTAS, 128, G_SMEM>>>(avf, wo, bo, x, Tb, nullptr);
    ln_kernel<true><<<MROWS, 256>>>(Tb, ln1s, ln1b, Hb, hf);

    // FFN
    gemm_mma<4><<<NSM_CTAS, 128, G_SMEM>>>(hf, w1, b1, nullptr, nullptr, ff);
    gemm_mma<2><<<NSM_CTAS, 128, G_SMEM>>>(ff, w2, b2, Hb, Tb, nullptr);
    ln_kernel<false><<<MROWS, 256>>>(Tb, ln2s, ln2b, out, nullptr);
}